// round 3
// baseline (speedup 1.0000x reference)
#include <cuda_runtime.h>
#include <cuda_bf16.h>
#include <cstdint>
#include <cstddef>

// Problem dims (fixed by the problem instance)
#define MM 4096   // B*S
#define NN 4096
#define KK 4096
#define NBLK 128  // N / 32
#define KBLK 128  // K / 32

// GEMM tiling
#define BM 256
#define BN 32
#define STAGE_A (BM * 128)          // 32768 B : BM rows x 32 fp32(tf32) = 128B
#define STAGE_W (BN * 128)          // 4096 B
#define STAGE_BYTES (STAGE_A + STAGE_W)
#define GEMM_SMEM (2 * STAGE_BYTES) // 73728 B, double buffered

// ---------------------------------------------------------------------------
// Scratch: tf32-rounded copies of A and W, block mask, compacted lists
// ---------------------------------------------------------------------------
__device__ float          g_At[(size_t)MM * KK];   // tf32-rounded data
__device__ float          g_Wt[(size_t)NN * KK];   // tf32-rounded weight
__device__ int            g_bm[NBLK * KBLK];
__device__ int            g_cnt[NBLK];
__device__ unsigned char  g_list[NBLK * KBLK];

// ---------------------------------------------------------------------------
// PTX helpers (base sm_100 ISA: cp.async / lds / mma.sync tf32)
// ---------------------------------------------------------------------------
static __device__ __forceinline__ uint32_t smem_u32(const void* p) {
    return (uint32_t)__cvta_generic_to_shared(p);
}
static __device__ __forceinline__ void cp16(uint32_t dst, const void* src) {
    asm volatile("cp.async.cg.shared.global [%0], [%1], 16;" :: "r"(dst), "l"(src));
}
static __device__ __forceinline__ void cp_commit() {
    asm volatile("cp.async.commit_group;" ::: "memory");
}
template <int N> static __device__ __forceinline__ void cp_wait() {
    asm volatile("cp.async.wait_group %0;" :: "n"(N) : "memory");
}
static __device__ __forceinline__ uint32_t lds32(uint32_t addr) {
    uint32_t v;
    asm volatile("ld.shared.b32 %0, [%1];" : "=r"(v) : "r"(addr));
    return v;
}
static __device__ __forceinline__ void mma_tf32(float* c, const uint32_t* a,
                                                uint32_t b0, uint32_t b1) {
    asm volatile(
        "mma.sync.aligned.m16n8k8.row.col.f32.tf32.tf32.f32 "
        "{%0,%1,%2,%3}, {%4,%5,%6,%7}, {%8,%9}, {%0,%1,%2,%3};"
        : "+f"(c[0]), "+f"(c[1]), "+f"(c[2]), "+f"(c[3])
        : "r"(a[0]), "r"(a[1]), "r"(a[2]), "r"(a[3]), "r"(b0), "r"(b1));
}
static __device__ __forceinline__ uint32_t to_tf32(float x) {
    uint32_t r;
    asm("cvt.rna.tf32.f32 %0, %1;" : "=r"(r) : "f"(x));
    return r;
}

// ---------------------------------------------------------------------------
// Kernel 1/2: fp32 -> tf32-rounded fp32 (round-to-nearest; avoids the
// truncation bias the MMA unit would otherwise introduce).
// ---------------------------------------------------------------------------
static __device__ __forceinline__ void conv_body(const float* __restrict__ src,
                                                 float* __restrict__ dst) {
    size_t i = (size_t)blockIdx.x * blockDim.x + threadIdx.x;   // exact grid
    float4 v = ((const float4*)src)[i];
    uint4 o;
    o.x = to_tf32(v.x);
    o.y = to_tf32(v.y);
    o.z = to_tf32(v.z);
    o.w = to_tf32(v.w);
    ((uint4*)dst)[i] = o;
}
__global__ void k_convA(const float* __restrict__ src) { conv_body(src, g_At); }
__global__ void k_convW(const float* __restrict__ src) { conv_body(src, g_Wt); }

// ---------------------------------------------------------------------------
// Kernel 3: block mask reduce. One CTA per 32x32 tile (grid = (KBLK, NBLK)).
// ---------------------------------------------------------------------------
__global__ void k_mask(const int* __restrict__ mask) {
    int nb = blockIdx.y, kb = blockIdx.x;
    int t = threadIdx.x;                  // 256 threads, int4 each = 1024 ints
    int r = t >> 3;
    int c = (t & 7) * 4;
    const int4 v = *(const int4*)&mask[(size_t)(nb * 32 + r) * KK + kb * 32 + c];
    int any = __syncthreads_or((v.x | v.y | v.z | v.w) != 0);
    if (t == 0) g_bm[nb * KBLK + kb] = any;
}

// ---------------------------------------------------------------------------
// Kernel 4: build per-nb compacted active-kb lists. 1 CTA, 128 threads.
// ---------------------------------------------------------------------------
__global__ void k_lists() {
    int nb = threadIdx.x;
    int c = 0;
    for (int kb = 0; kb < KBLK; kb++)
        if (g_bm[nb * KBLK + kb]) g_list[nb * KBLK + (c++)] = (unsigned char)kb;
    g_cnt[nb] = c;
}

// ---------------------------------------------------------------------------
// Kernel 5: sparse GEMM via mma.sync m16n8k8 tf32 (fp32 accum).
// CTA: M=256 x N=32, 256 threads (8 warps, each a 32x32 output tile).
// Per active kb: 32 k = 4 k8-steps. cp.async double-buffered.
// SMEM rows are 128B with XOR swizzle: 16B unit u -> u ^ (row & 7).
// Fragments via LDS.32; all 32 lanes hit 32 distinct banks (verified).
// ---------------------------------------------------------------------------
__global__ void __launch_bounds__(256) k_gemm(const float* __restrict__ bias,
                                              float* __restrict__ out) {
    extern __shared__ unsigned char smem[];
    const uint32_t sbase = smem_u32(smem);

    const int tid = threadIdx.x;
    const int lid = tid & 31;
    const int wid = tid >> 5;              // 0..7, warp owns rows wid*32..+31
    const int l4 = lid & 3;                // k-lane within fragment
    const int l2 = lid >> 2;               // row-lane within fragment (0..7)
    const int mt = blockIdx.x;             // 0..15
    const int nb = blockIdx.y;             // 0..127
    const int cnt = g_cnt[nb];
    const unsigned char* list = g_list + nb * KBLK;

    const float* Abase = g_At + (size_t)(mt * BM) * KK;
    const float* Wbase = g_Wt + (size_t)(nb * BN) * KK;

    // Fragment LDS addressing constants.
    // addr(r, c) = tile + r*128 + (((c>>2)*16) ^ ((r&7)*16)) + (c&3)*4
    // A rows: wid*32 + tm*16 + l2 (+8 for the second half — same r&7).
    uint32_t a_base[2];
    #pragma unroll
    for (int tm = 0; tm < 2; tm++)
        a_base[tm] = (uint32_t)(wid * 32 + tm * 16 + l2) * 128u;
    const uint32_t a_sw = (uint32_t)(l2 & 7) * 16u;   // l2 in 0..7
    const uint32_t lane_b = (uint32_t)l4 * 4u;
    // W rows: tn*8 + l2 (tn*8 leaves r&7 = l2 unchanged).
    uint32_t b_base[4];
    #pragma unroll
    for (int tn = 0; tn < 4; tn++)
        b_base[tn] = (uint32_t)(tn * 8 + l2) * 128u;

    float acc[2][4][4];
    #pragma unroll
    for (int tm = 0; tm < 2; tm++)
        #pragma unroll
        for (int tn = 0; tn < 4; tn++)
            #pragma unroll
            for (int e = 0; e < 4; e++) acc[tm][tn][e] = 0.0f;

    // --- tile loader (cp.async): 32 fp32 = 8 x 16B units per row ---
    auto load_tiles = [&](int stage, int kb) {
        const uint32_t sb = sbase + (uint32_t)stage * STAGE_BYTES;
        const float* Asrc = Abase + (size_t)kb * 32;
        #pragma unroll
        for (int it = 0; it < 8; it++) {           // 2048 x 16B A units
            int idx = it * 256 + tid;
            int r = idx >> 3, j = idx & 7;
            uint32_t off = (uint32_t)(r * 128 + j * 16);
            off ^= (off >> 3) & 0x70u;
            cp16(sb + off, Asrc + (size_t)r * KK + j * 4);
        }
        {                                           // 256 x 16B W units
            int r = tid >> 3, j = tid & 7;
            uint32_t off = (uint32_t)(r * 128 + j * 16);
            off ^= (off >> 3) & 0x70u;
            cp16(sb + STAGE_A + off, Wbase + (size_t)kb * 32 + (size_t)r * KK + j * 4);
        }
    };

    auto compute = [&](int stage) {
        const uint32_t sA = sbase + (uint32_t)stage * STAGE_BYTES;
        const uint32_t sW = sA + STAGE_A;
        #pragma unroll
        for (int ks = 0; ks < 4; ks++) {
            const uint32_t u0 = ((uint32_t)(ks * 2 + 0) * 16u);
            const uint32_t u1 = ((uint32_t)(ks * 2 + 1) * 16u);
            uint32_t a[2][4];
            #pragma unroll
            for (int tm = 0; tm < 2; tm++) {
                const uint32_t c0 = (u0 ^ a_sw) + lane_b;
                const uint32_t c1 = (u1 ^ a_sw) + lane_b;
                a[tm][0] = lds32(sA + a_base[tm] + c0);            // (r,   k)
                a[tm][1] = lds32(sA + a_base[tm] + 1024u + c0);    // (r+8, k)
                a[tm][2] = lds32(sA + a_base[tm] + c1);            // (r,   k+4)
                a[tm][3] = lds32(sA + a_base[tm] + 1024u + c1);    // (r+8, k+4)
            }
            uint32_t b[4][2];
            #pragma unroll
            for (int tn = 0; tn < 4; tn++) {
                b[tn][0] = lds32(sW + b_base[tn] + (u0 ^ a_sw) + lane_b);
                b[tn][1] = lds32(sW + b_base[tn] + (u1 ^ a_sw) + lane_b);
            }
            #pragma unroll
            for (int tm = 0; tm < 2; tm++)
                #pragma unroll
                for (int tn = 0; tn < 4; tn++)
                    mma_tf32(acc[tm][tn], a[tm], b[tn][0], b[tn][1]);
        }
    };

    // --- double-buffered mainloop over active kb list ---
    if (cnt > 0) { load_tiles(0, list[0]); cp_commit(); }
    for (int i = 0; i < cnt; i++) {
        if (i + 1 < cnt) {
            load_tiles((i + 1) & 1, list[i + 1]);
            cp_commit();
            cp_wait<1>();
        } else {
            cp_wait<0>();
        }
        __syncthreads();
        compute(i & 1);
        __syncthreads();
    }

    // --- epilogue: add bias, store float2 per fragment half ---
    float2 bv[4];
    #pragma unroll
    for (int tn = 0; tn < 4; tn++)
        bv[tn] = *(const float2*)&bias[nb * BN + tn * 8 + l4 * 2];

    #pragma unroll
    for (int tm = 0; tm < 2; tm++) {
        #pragma unroll
        for (int h = 0; h < 2; h++) {
            const int m = mt * BM + wid * 32 + tm * 16 + l2 + h * 8;
            float* orow = out + (size_t)m * NN + nb * BN + l4 * 2;
            #pragma unroll
            for (int tn = 0; tn < 4; tn++) {
                float2 v;
                v.x = acc[tm][tn][h * 2 + 0] + bv[tn].x;
                v.y = acc[tm][tn][h * 2 + 1] + bv[tn].y;
                *(float2*)(orow + tn * 8) = v;
            }
        }
    }
}

// ---------------------------------------------------------------------------
// Launch: conv A, conv W, block-mask, lists, sparse GEMM (all graph-capturable)
// ---------------------------------------------------------------------------
extern "C" void kernel_launch(void* const* d_in, const int* in_sizes, int n_in,
                              void* d_out, int out_size) {
    const float* data   = (const float*)d_in[0];   // [B, S, K] = [M, K]
    const int*   mask   = (const int*)d_in[1];     // [N, K]
    const float* weight = (const float*)d_in[2];   // [N, K]
    const float* bias   = (const float*)d_in[3];   // [N]
    float* out = (float*)d_out;                    // [M, N]

    cudaFuncSetAttribute(k_gemm, cudaFuncAttributeMaxDynamicSharedMemorySize, GEMM_SMEM);

    k_convA<<<(MM * KK / 4) / 256, 256>>>(data);
    k_convW<<<(NN * KK / 4) / 256, 256>>>(weight);
    k_mask<<<dim3(KBLK, NBLK), 256>>>(mask);
    k_lists<<<1, NBLK>>>();
    k_gemm<<<dim3(MM / BM, NBLK), 256, GEMM_SMEM>>>(bias, out);
}

// round 4
// speedup vs baseline: 1.1099x; 1.1099x over previous
#include <cuda_runtime.h>
#include <cuda_bf16.h>
#include <cstdint>
#include <cstddef>

// Problem dims (fixed by the problem instance)
#define MM 4096   // B*S
#define NN 4096
#define KK 4096
#define NBLK 128  // N / 32
#define KBLK 128  // K / 32
#define NPAIR 64  // N / 64 (nb pairs)

// GEMM tiling: CTA = 256 rows x 64 cols (2 nb blocks), 256 threads / 8 warps.
#define BM 256
#define STAGE_A (BM * 128)          // 32768 B : BM rows x 32 tf32 = 128B
#define STAGE_W (2 * 32 * 128)      // 8192 B  : 2 halves x 32 rows x 128B
#define STAGE_BYTES (STAGE_A + STAGE_W)          // 40960
#define SMEM_LIST (2 * STAGE_BYTES)              // 81920
#define GEMM_SMEM (SMEM_LIST + KBLK * 4)         // + 512B list

// ---------------------------------------------------------------------------
// Scratch: tf32-rounded copies of A and W, block mask, per-pair union lists
// ---------------------------------------------------------------------------
__device__ float          g_At[(size_t)MM * KK];   // tf32-rounded data
__device__ float          g_Wt[(size_t)NN * KK];   // tf32-rounded weight
__device__ int            g_bm[NBLK * KBLK];
__device__ int            g_cntp[NPAIR];
__device__ uint32_t       g_listp[NPAIR * KBLK];  // kb | f0<<8 | f1<<9

// ---------------------------------------------------------------------------
// PTX helpers (base sm_100 ISA: cp.async / lds / mma.sync tf32)
// ---------------------------------------------------------------------------
static __device__ __forceinline__ uint32_t smem_u32(const void* p) {
    return (uint32_t)__cvta_generic_to_shared(p);
}
static __device__ __forceinline__ void cp16(uint32_t dst, const void* src) {
    asm volatile("cp.async.cg.shared.global [%0], [%1], 16;" :: "r"(dst), "l"(src));
}
static __device__ __forceinline__ void cp_commit() {
    asm volatile("cp.async.commit_group;" ::: "memory");
}
template <int N> static __device__ __forceinline__ void cp_wait() {
    asm volatile("cp.async.wait_group %0;" :: "n"(N) : "memory");
}
static __device__ __forceinline__ uint32_t lds32(uint32_t addr) {
    uint32_t v;
    asm volatile("ld.shared.b32 %0, [%1];" : "=r"(v) : "r"(addr));
    return v;
}
static __device__ __forceinline__ void mma_tf32(float* c, const uint32_t* a,
                                                uint32_t b0, uint32_t b1) {
    asm volatile(
        "mma.sync.aligned.m16n8k8.row.col.f32.tf32.tf32.f32 "
        "{%0,%1,%2,%3}, {%4,%5,%6,%7}, {%8,%9}, {%0,%1,%2,%3};"
        : "+f"(c[0]), "+f"(c[1]), "+f"(c[2]), "+f"(c[3])
        : "r"(a[0]), "r"(a[1]), "r"(a[2]), "r"(a[3]), "r"(b0), "r"(b1));
}
static __device__ __forceinline__ uint32_t to_tf32(float x) {
    uint32_t r;
    asm("cvt.rna.tf32.f32 %0, %1;" : "=r"(r) : "f"(x));
    return r;
}

// ---------------------------------------------------------------------------
// Kernel 1/2: fp32 -> tf32-rounded fp32 (round-to-nearest, avoids MMA
// truncation bias). One float4 per thread, exact grid.
// ---------------------------------------------------------------------------
static __device__ __forceinline__ void conv_body(const float* __restrict__ src,
                                                 float* __restrict__ dst) {
    size_t i = (size_t)blockIdx.x * blockDim.x + threadIdx.x;
    float4 v = ((const float4*)src)[i];
    uint4 o;
    o.x = to_tf32(v.x);
    o.y = to_tf32(v.y);
    o.z = to_tf32(v.z);
    o.w = to_tf32(v.w);
    ((uint4*)dst)[i] = o;
}
__global__ void k_convA(const float* __restrict__ src) { conv_body(src, g_At); }
__global__ void k_convW(const float* __restrict__ src) { conv_body(src, g_Wt); }

// ---------------------------------------------------------------------------
// Kernel 3: block mask reduce. One CTA per 32x32 tile (grid = (KBLK, NBLK)).
// ---------------------------------------------------------------------------
__global__ void k_mask(const int* __restrict__ mask) {
    int nb = blockIdx.y, kb = blockIdx.x;
    int t = threadIdx.x;                  // 256 threads, int4 each = 1024 ints
    int r = t >> 3;
    int c = (t & 7) * 4;
    const int4 v = *(const int4*)&mask[(size_t)(nb * 32 + r) * KK + kb * 32 + c];
    int any = __syncthreads_or((v.x | v.y | v.z | v.w) != 0);
    if (t == 0) g_bm[nb * KBLK + kb] = any;
}

// ---------------------------------------------------------------------------
// Kernel 4: per-pair union lists via warp ballot. grid = NPAIR CTAs x 32.
// Entry: kb | f0<<8 | f1<<9 (f0/f1 = halves' activity at this kb).
// ---------------------------------------------------------------------------
__global__ void k_lists() {
    const int nbg = blockIdx.x;
    const int lane = threadIdx.x;
    const int* bm0 = g_bm + (2 * nbg + 0) * KBLK;
    const int* bm1 = g_bm + (2 * nbg + 1) * KBLK;
    int cnt = 0;
    #pragma unroll
    for (int step = 0; step < KBLK / 32; step++) {
        int kb = step * 32 + lane;
        int f0 = bm0[kb], f1 = bm1[kb];
        int act = (f0 | f1) != 0;
        unsigned m = __ballot_sync(0xFFFFFFFFu, act);
        if (act) {
            int pos = cnt + __popc(m & ((1u << lane) - 1u));
            g_listp[nbg * KBLK + pos] =
                (uint32_t)kb | ((uint32_t)(f0 != 0) << 8) | ((uint32_t)(f1 != 0) << 9);
        }
        cnt += __popc(m);
    }
    if (lane == 0) g_cntp[nbg] = cnt;
}

// ---------------------------------------------------------------------------
// Kernel 5: sparse GEMM via mma.sync m16n8k8 tf32 (fp32 accum).
// CTA: M=256 x N=64 (2 nb halves, per-half kb skip). 8 warps, each 32x64.
// Double-buffered cp.async, ONE __syncthreads per kb iteration.
// SMEM rows 128B, XOR swizzle: 16B unit u -> u ^ (row & 7).
// ---------------------------------------------------------------------------
__global__ void __launch_bounds__(256, 2) k_gemm(const float* __restrict__ bias,
                                                 float* __restrict__ out) {
    extern __shared__ unsigned char smem[];
    const uint32_t sbase = smem_u32(smem);
    uint32_t* slist = (uint32_t*)(smem + SMEM_LIST);

    const int tid = threadIdx.x;
    const int lid = tid & 31;
    const int wid = tid >> 5;              // warp owns rows wid*32..+31
    const int l4 = lid & 3;                // k-lane
    const int l2 = lid >> 2;               // row-lane (0..7)
    const int nbg = blockIdx.x;            // 0..63 (nb pair)
    const int mt = blockIdx.y;             // 0..15
    const int cnt = g_cntp[nbg];

    // Preload compacted list into smem.
    if (tid < KBLK && tid < cnt) slist[tid] = g_listp[nbg * KBLK + tid];

    const float* Abase = g_At + (size_t)(mt * BM) * KK;
    const float* Wbase = g_Wt + (size_t)(nbg * 64) * KK;   // 64 rows (2 halves)

    // Fragment LDS addressing: addr(r,c)= r*128 + (((c>>2)*16)^((r&7)*16)) + (c&3)*4
    uint32_t a_base[2];
    #pragma unroll
    for (int tm = 0; tm < 2; tm++)
        a_base[tm] = (uint32_t)(wid * 32 + tm * 16 + l2) * 128u;
    const uint32_t a_sw = (uint32_t)l2 * 16u;
    const uint32_t lane_b = (uint32_t)l4 * 4u;
    uint32_t b_base[4];                     // rows tn*8 + l2 within a 32-row half
    #pragma unroll
    for (int tn = 0; tn < 4; tn++)
        b_base[tn] = (uint32_t)(tn * 8 + l2) * 128u;

    float acc[2][8][4];                     // [tm][h*4+tn][frag]
    #pragma unroll
    for (int tm = 0; tm < 2; tm++)
        #pragma unroll
        for (int tn = 0; tn < 8; tn++)
            #pragma unroll
            for (int e = 0; e < 4; e++) acc[tm][tn][e] = 0.0f;

    // --- tile loader (cp.async) ---
    auto load_tiles = [&](int stage, uint32_t entry) {
        const int kb = (int)(entry & 0xFFu);
        const uint32_t sb = sbase + (uint32_t)stage * STAGE_BYTES;
        const float* Asrc = Abase + (size_t)kb * 32;
        #pragma unroll
        for (int it = 0; it < 8; it++) {           // 2048 x 16B A units
            int idx = it * 256 + tid;
            int r = idx >> 3, j = idx & 7;
            uint32_t off = (uint32_t)(r * 128 + j * 16);
            off ^= (off >> 3) & 0x70u;
            cp16(sb + off, Asrc + (size_t)r * KK + j * 4);
        }
        {                                           // W halves, active only
            int r = tid >> 3, j = tid & 7;
            uint32_t off = (uint32_t)(r * 128 + j * 16);
            off ^= (off >> 3) & 0x70u;
            const float* Wk = Wbase + (size_t)kb * 32;
            if (entry & 0x100u)
                cp16(sb + STAGE_A + off, Wk + (size_t)r * KK + j * 4);
            if (entry & 0x200u)
                cp16(sb + STAGE_A + 4096u + off,
                     Wk + (size_t)(32 + r) * KK + j * 4);
        }
    };

    auto compute = [&](int stage, uint32_t entry) {
        const uint32_t sA = sbase + (uint32_t)stage * STAGE_BYTES;
        const uint32_t sW = sA + STAGE_A;
        const bool f0 = (entry & 0x100u) != 0;
        const bool f1 = (entry & 0x200u) != 0;
        #pragma unroll
        for (int ks = 0; ks < 4; ks++) {
            const uint32_t u0 = (uint32_t)(ks * 2 + 0) * 16u;
            const uint32_t u1 = (uint32_t)(ks * 2 + 1) * 16u;
            const uint32_t c0 = (u0 ^ a_sw) + lane_b;
            const uint32_t c1 = (u1 ^ a_sw) + lane_b;
            uint32_t a[2][4];
            #pragma unroll
            for (int tm = 0; tm < 2; tm++) {
                a[tm][0] = lds32(sA + a_base[tm] + c0);
                a[tm][1] = lds32(sA + a_base[tm] + 1024u + c0);
                a[tm][2] = lds32(sA + a_base[tm] + c1);
                a[tm][3] = lds32(sA + a_base[tm] + 1024u + c1);
            }
            #pragma unroll
            for (int h = 0; h < 2; h++) {
                if (h == 0 ? !f0 : !f1) continue;
                const uint32_t sWh = sW + (uint32_t)h * 4096u;
                uint32_t b[4][2];
                #pragma unroll
                for (int tn = 0; tn < 4; tn++) {
                    b[tn][0] = lds32(sWh + b_base[tn] + c0);
                    b[tn][1] = lds32(sWh + b_base[tn] + c1);
                }
                #pragma unroll
                for (int tm = 0; tm < 2; tm++)
                    #pragma unroll
                    for (int tn = 0; tn < 4; tn++)
                        mma_tf32(acc[tm][h * 4 + tn], a[tm], b[tn][0], b[tn][1]);
            }
        }
    };

    __syncthreads();                       // slist visible
    if (cnt > 0) { load_tiles(0, slist[0]); cp_commit(); }
    for (int i = 0; i < cnt; i++) {
        const uint32_t entry = slist[i];
        cp_wait<0>();
        __syncthreads();                   // buf i ready; prev compute done
        if (i + 1 < cnt) { load_tiles((i + 1) & 1, slist[i + 1]); cp_commit(); }
        compute(i & 1, entry);
    }

    // --- epilogue: add bias, float2 stores ---
    float2 bv[8];
    #pragma unroll
    for (int tn = 0; tn < 8; tn++)
        bv[tn] = *(const float2*)&bias[nbg * 64 + tn * 8 + l4 * 2];

    #pragma unroll
    for (int tm = 0; tm < 2; tm++) {
        #pragma unroll
        for (int h = 0; h < 2; h++) {
            const int m = mt * BM + wid * 32 + tm * 16 + l2 + h * 8;
            float* orow = out + (size_t)m * NN + nbg * 64 + l4 * 2;
            #pragma unroll
            for (int tn = 0; tn < 8; tn++) {
                float2 v;
                v.x = acc[tm][tn][h * 2 + 0] + bv[tn].x;
                v.y = acc[tm][tn][h * 2 + 1] + bv[tn].y;
                *(float2*)(orow + tn * 8) = v;
            }
        }
    }
}

// ---------------------------------------------------------------------------
// Launch: conv A, conv W, block-mask, lists, sparse GEMM (graph-capturable)
// ---------------------------------------------------------------------------
extern "C" void kernel_launch(void* const* d_in, const int* in_sizes, int n_in,
                              void* d_out, int out_size) {
    const float* data   = (const float*)d_in[0];   // [B, S, K] = [M, K]
    const int*   mask   = (const int*)d_in[1];     // [N, K]
    const float* weight = (const float*)d_in[2];   // [N, K]
    const float* bias   = (const float*)d_in[3];   // [N]
    float* out = (float*)d_out;                    // [M, N]

    cudaFuncSetAttribute(k_gemm, cudaFuncAttributeMaxDynamicSharedMemorySize, GEMM_SMEM);

    k_convA<<<(MM * KK / 4) / 256, 256>>>(data);
    k_convW<<<(NN * KK / 4) / 256, 256>>>(weight);
    k_mask<<<dim3(KBLK, NBLK), 256>>>(mask);
    k_lists<<<NPAIR, 32>>>();
    k_gemm<<<dim3(NPAIR, MM / BM), 256, GEMM_SMEM>>>(bias, out);
}